// round 11
// baseline (speedup 1.0000x reference)
#include <cuda_runtime.h>
#include <cuda_fp16.h>

#define N_NODES 100000
#define N_EDGES 1600000
#define IN_CH 128
#define HID1 64
#define HID2 64
#define HID3 256
#define OUT_CH 64
#define SCAN_NB ((N_NODES + 1023) / 1024)   // 98

// ---------------- scratch (device globals; no allocation allowed) ----------------
__device__ float g_deg[N_NODES];
__device__ float g_dinv[N_NODES];
__device__ int   g_rs[N_NODES];                // CSR row start (exclusive scan)
__device__ int   g_cur[N_NODES];               // scatter cursors
__device__ int   g_bsum[128];                  // per-block scan sums
__device__ int   g_boff[128];                  // per-block offsets
__device__ int2  g_csr[N_EDGES];               // {src, norm-as-bits} grouped by dst
__device__ __half g_h16[(size_t)N_NODES * 64]; // fp16 GEMM output (gather source)
__device__ float g_h2[(size_t)N_NODES * 64];   // fp32 agg output
__device__ float g_W34[64 * 64];               // W3 @ W4 collapsed weight
__device__ float g_b34[64];                    // b3 @ W4 + b4
__device__ int   g_is64;                       // edge_index dtype flag

// ---------------- index dtype detection ----------------
__global__ void k_detect(const int* ei) {
    if (threadIdx.x == 0 && blockIdx.x == 0) {
        int is64 = 1;
        #pragma unroll 1
        for (int i = 0; i < 64; i++) {
            if (ei[2 * i + 1] != 0) { is64 = 0; break; }
        }
        g_is64 = is64;
    }
}

__device__ __forceinline__ int load_idx(const void* ei, long long i, int is64) {
    if (is64) return (int)__ldg(((const long long*)ei) + i);
    return __ldg(((const int*)ei) + i);
}

// ---------------- degree ----------------
__global__ void k_deg(const void* __restrict__ ei) {
    int e = blockIdx.x * blockDim.x + threadIdx.x;
    if (e >= N_EDGES) return;
    int d = load_idx(ei, (long long)N_EDGES + e, g_is64);
    atomicAdd(&g_deg[d], 1.0f);
}

// ---------------- collapse layers 3+4: W34 = W3@W4, b34 = b3@W4 + b4 ----------------
__global__ __launch_bounds__(64) void k_w34(const float* __restrict__ W3,
                                            const float* __restrict__ b3,
                                            const float* __restrict__ W4,
                                            const float* __restrict__ b4) {
    int i = blockIdx.x;
    int j = threadIdx.x;
    const float* w3r = W3 + (size_t)i * HID3;
    float acc = 0.0f;
    #pragma unroll 8
    for (int k = 0; k < HID3; k++) acc += w3r[k] * W4[(size_t)k * OUT_CH + j];
    g_W34[i * 64 + j] = acc;
    if (i == 0) {
        float bb = 0.0f;
        #pragma unroll 8
        for (int k = 0; k < HID3; k++) bb += b3[k] * W4[(size_t)k * OUT_CH + j];
        g_b34[j] = bb + b4[j];
    }
}

// ---------------- scan phase 1 (+ fused dinv) ----------------
__global__ __launch_bounds__(1024) void k_scan1() {
    __shared__ int s[1024];
    int t = threadIdx.x;
    int i = blockIdx.x * 1024 + t;
    float dg = (i < N_NODES) ? g_deg[i] : 0.0f;
    int v = (int)dg;
    if (i < N_NODES) g_dinv[i] = rsqrtf(dg + 1.0f);
    s[t] = v;
    __syncthreads();
    #pragma unroll 1
    for (int off = 1; off < 1024; off <<= 1) {
        int x = (t >= off) ? s[t - off] : 0;
        __syncthreads();
        s[t] += x;
        __syncthreads();
    }
    if (i < N_NODES) g_rs[i] = s[t] - v;   // exclusive within block
    if (t == 1023) g_bsum[blockIdx.x] = s[1023];
}

__global__ __launch_bounds__(128) void k_scan2() {
    __shared__ int s[128];
    int t = threadIdx.x;
    int v = (t < SCAN_NB) ? g_bsum[t] : 0;
    s[t] = v;
    __syncthreads();
    #pragma unroll 1
    for (int off = 1; off < 128; off <<= 1) {
        int x = (t >= off) ? s[t - off] : 0;
        __syncthreads();
        s[t] += x;
        __syncthreads();
    }
    if (t < SCAN_NB) g_boff[t] = s[t] - v;
}

__global__ __launch_bounds__(1024) void k_scan3() {
    int i = blockIdx.x * 1024 + threadIdx.x;
    if (i >= N_NODES) return;
    int r = g_rs[i] + g_boff[blockIdx.x];
    g_rs[i] = r;
    g_cur[i] = r;
}

// ---------------- fill CSR ----------------
__global__ void k_fill(const void* __restrict__ ei) {
    int e = blockIdx.x * blockDim.x + threadIdx.x;
    if (e >= N_EDGES) return;
    int is64 = g_is64;
    int s = load_idx(ei, e, is64);
    int d = load_idx(ei, (long long)N_EDGES + e, is64);
    float norm = g_dinv[s] * g_dinv[d];
    int pos = atomicAdd(&g_cur[d], 1);
    g_csr[pos] = make_int2(s, __float_as_int(norm));
}

// ---------------- fused aggregate + self-loop + bias + relu ----------------
// Gather source is fp16 (64 ch = 128B = ONE L2 line per row). One warp per dst;
// each lane owns channel pair (2*lane, 2*lane+1); accumulate fp32.
__global__ __launch_bounds__(256) void k_agg(const __half* __restrict__ h,
                                             const float* __restrict__ bias,
                                             float* __restrict__ out) {
    int warp = (int)((blockIdx.x * 256 + threadIdx.x) >> 5);
    int lane = threadIdx.x & 31;
    if (warp >= N_NODES) return;
    int i = warp;
    int start = g_rs[i];
    int end = start + (int)g_deg[i];
    float di = g_dinv[i];
    float sl = di * di;
    const __half2* hrow = (const __half2*)(h + ((size_t)i << 6));
    float2 hs = __half22float2(hrow[lane]);
    float acc0 = hs.x * sl;
    float acc1 = hs.y * sl;
    int e = start;
    for (; e + 3 < end; e += 4) {
        int2 r0 = __ldg(&g_csr[e + 0]);
        int2 r1 = __ldg(&g_csr[e + 1]);
        int2 r2 = __ldg(&g_csr[e + 2]);
        int2 r3 = __ldg(&g_csr[e + 3]);
        float2 v0 = __half22float2(((const __half2*)(h + ((size_t)r0.x << 6)))[lane]);
        float2 v1 = __half22float2(((const __half2*)(h + ((size_t)r1.x << 6)))[lane]);
        float2 v2 = __half22float2(((const __half2*)(h + ((size_t)r2.x << 6)))[lane]);
        float2 v3 = __half22float2(((const __half2*)(h + ((size_t)r3.x << 6)))[lane]);
        float n0 = __int_as_float(r0.y), n1 = __int_as_float(r1.y);
        float n2 = __int_as_float(r2.y), n3 = __int_as_float(r3.y);
        acc0 += v0.x * n0; acc1 += v0.y * n0;
        acc0 += v1.x * n1; acc1 += v1.y * n1;
        acc0 += v2.x * n2; acc1 += v2.y * n2;
        acc0 += v3.x * n3; acc1 += v3.y * n3;
    }
    for (; e < end; e++) {
        int2 r = __ldg(&g_csr[e]);
        float n = __int_as_float(r.y);
        float2 v = __half22float2(((const __half2*)(h + ((size_t)r.x << 6)))[lane]);
        acc0 += v.x * n;
        acc1 += v.y * n;
    }
    float2 bv = ((const float2*)bias)[lane];
    float2 o;
    o.x = fmaxf(acc0 + bv.x, 0.0f);
    o.y = fmaxf(acc1 + bv.y, 0.0f);
    ((float2*)(out + ((size_t)i << 6)))[lane] = o;
}

// ---------------- SGEMM: C[N,NOUT] = A[N,K] @ W[K,NOUT] (+bias) (fp16 out | lsm) ----------------
// BM=128, BN=64, BK=16, 256 threads, 8x4 microtile, double-buffered smem.
// C16 != nullptr: write packed fp16 (for gather layers); else fp32.
// lsm=1 requires NOUT==64 and gridDim.y==1.
__global__ __launch_bounds__(256) void k_gemm(const float* __restrict__ A,
                                              const float* __restrict__ W,
                                              const float* __restrict__ bias,
                                              float* __restrict__ C,
                                              __half* __restrict__ C16,
                                              int N, int K, int NOUT, int lsm) {
    __shared__ float As[2][16][128];
    __shared__ float Bs[2][16][64];

    int r0 = blockIdx.x * 128;
    int c0 = blockIdx.y * 64;
    int tid = threadIdx.x;
    int tx = tid & 15;
    int ty = tid >> 4;

    int arow = tid >> 1;
    int ak8  = (tid & 1) << 3;
    int wrow = tid >> 4;
    int wc4  = (tid & 15) << 2;

    float acc[8][4];
    #pragma unroll
    for (int i = 0; i < 8; i++)
        #pragma unroll
        for (int j = 0; j < 4; j++) acc[i][j] = 0.0f;

    int nsteps = K >> 4;
    int gr_a = r0 + arow;

    // preload tile 0
    {
        float4 a0 = make_float4(0.f, 0.f, 0.f, 0.f);
        float4 a1 = make_float4(0.f, 0.f, 0.f, 0.f);
        if (gr_a < N) {
            const float* ap = A + (size_t)gr_a * K + ak8;
            a0 = *(const float4*)ap;
            a1 = *(const float4*)(ap + 4);
        }
        As[0][ak8 + 0][arow] = a0.x; As[0][ak8 + 1][arow] = a0.y;
        As[0][ak8 + 2][arow] = a0.z; As[0][ak8 + 3][arow] = a0.w;
        As[0][ak8 + 4][arow] = a1.x; As[0][ak8 + 5][arow] = a1.y;
        As[0][ak8 + 6][arow] = a1.z; As[0][ak8 + 7][arow] = a1.w;
        *(float4*)&Bs[0][wrow][wc4] = *(const float4*)&W[(size_t)wrow * NOUT + c0 + wc4];
    }
    __syncthreads();

    for (int t = 0; t < nsteps; t++) {
        int cur = t & 1;
        float4 a0, a1, wv;
        bool have_next = (t + 1 < nsteps);
        if (have_next) {
            int kk = (t + 1) << 4;
            a0 = make_float4(0.f, 0.f, 0.f, 0.f);
            a1 = make_float4(0.f, 0.f, 0.f, 0.f);
            if (gr_a < N) {
                const float* ap = A + (size_t)gr_a * K + kk + ak8;
                a0 = *(const float4*)ap;
                a1 = *(const float4*)(ap + 4);
            }
            wv = *(const float4*)&W[(size_t)(kk + wrow) * NOUT + c0 + wc4];
        }

        #pragma unroll
        for (int k = 0; k < 16; k++) {
            float4 b = *(const float4*)&Bs[cur][k][tx * 4];
            float ar[8];
            #pragma unroll
            for (int i = 0; i < 8; i++) ar[i] = As[cur][k][ty * 8 + i];
            #pragma unroll
            for (int i = 0; i < 8; i++) {
                acc[i][0] += ar[i] * b.x;
                acc[i][1] += ar[i] * b.y;
                acc[i][2] += ar[i] * b.z;
                acc[i][3] += ar[i] * b.w;
            }
        }

        if (have_next) {
            int nxt = cur ^ 1;
            As[nxt][ak8 + 0][arow] = a0.x; As[nxt][ak8 + 1][arow] = a0.y;
            As[nxt][ak8 + 2][arow] = a0.z; As[nxt][ak8 + 3][arow] = a0.w;
            As[nxt][ak8 + 4][arow] = a1.x; As[nxt][ak8 + 5][arow] = a1.y;
            As[nxt][ak8 + 6][arow] = a1.z; As[nxt][ak8 + 7][arow] = a1.w;
            *(float4*)&Bs[nxt][wrow][wc4] = wv;
            __syncthreads();
        }
    }

    float4 bv = make_float4(0.f, 0.f, 0.f, 0.f);
    if (bias) bv = *(const float4*)&bias[c0 + tx * 4];

    if (lsm) {
        // fused log_softmax over the 64 cols of each row (16 tx lanes x 4 cols,
        // within one half-warp; xor offsets 8/4/2/1 stay inside the row).
        #pragma unroll
        for (int i = 0; i < 8; i++) {
            float v0 = acc[i][0] + bv.x;
            float v1 = acc[i][1] + bv.y;
            float v2 = acc[i][2] + bv.z;
            float v3 = acc[i][3] + bv.w;
            float m = fmaxf(fmaxf(v0, v1), fmaxf(v2, v3));
            #pragma unroll
            for (int o = 8; o; o >>= 1) m = fmaxf(m, __shfl_xor_sync(0xffffffffu, m, o));
            float s = expf(v0 - m) + expf(v1 - m) + expf(v2 - m) + expf(v3 - m);
            #pragma unroll
            for (int o = 8; o; o >>= 1) s += __shfl_xor_sync(0xffffffffu, s, o);
            float lse = m + logf(s);
            int gr = r0 + ty * 8 + i;
            if (gr < N) {
                *(float4*)&C[(size_t)gr * 64 + tx * 4] =
                    make_float4(v0 - lse, v1 - lse, v2 - lse, v3 - lse);
            }
        }
    } else if (C16) {
        #pragma unroll
        for (int i = 0; i < 8; i++) {
            int gr = r0 + ty * 8 + i;
            if (gr < N) {
                __half2 p[2];
                p[0] = __floats2half2_rn(acc[i][0] + bv.x, acc[i][1] + bv.y);
                p[1] = __floats2half2_rn(acc[i][2] + bv.z, acc[i][3] + bv.w);
                *(uint2*)&C16[(size_t)gr * NOUT + c0 + tx * 4] = *(uint2*)p;
            }
        }
    } else {
        #pragma unroll
        for (int i = 0; i < 8; i++) {
            int gr = r0 + ty * 8 + i;
            if (gr < N) {
                *(float4*)&C[(size_t)gr * NOUT + c0 + tx * 4] =
                    make_float4(acc[i][0] + bv.x, acc[i][1] + bv.y,
                                acc[i][2] + bv.z, acc[i][3] + bv.w);
            }
        }
    }
}

// ---------------- launch ----------------
extern "C" void kernel_launch(void* const* d_in, const int* in_sizes, int n_in,
                              void* d_out, int out_size) {
    const float* x  = (const float*)d_in[0];
    const void*  ei = d_in[1];
    const float* W1 = (const float*)d_in[2];
    const float* b1 = (const float*)d_in[3];
    const float* W2 = (const float*)d_in[4];
    const float* b2 = (const float*)d_in[5];
    const float* W3 = (const float*)d_in[6];
    const float* b3 = (const float*)d_in[7];
    const float* W4 = (const float*)d_in[8];
    const float* b4 = (const float*)d_in[9];
    float* out = (float*)d_out;

    void *p_deg, *p_h16, *p_h2, *p_w34, *p_b34;
    cudaGetSymbolAddress(&p_deg, g_deg);
    cudaGetSymbolAddress(&p_h16, g_h16);
    cudaGetSymbolAddress(&p_h2, g_h2);
    cudaGetSymbolAddress(&p_w34, g_W34);
    cudaGetSymbolAddress(&p_b34, g_b34);
    __half* h16 = (__half*)p_h16;
    float* h2   = (float*)p_h2;
    float* W34  = (float*)p_w34;
    float* b34  = (float*)p_b34;

    // Side stream + events for fork-join (created once, pre-capture). Fallback
    // to serial single-stream ordering if creation fails.
    static cudaStream_t s2 = nullptr;
    static cudaEvent_t ev_fork = nullptr, ev_join = nullptr;
    static int use_fork = -1;
    if (use_fork < 0) {
        use_fork = 1;
        if (cudaStreamCreateWithFlags(&s2, cudaStreamNonBlocking) != cudaSuccess) use_fork = 0;
        if (use_fork && cudaEventCreateWithFlags(&ev_fork, cudaEventDisableTiming) != cudaSuccess) use_fork = 0;
        if (use_fork && cudaEventCreateWithFlags(&ev_join, cudaEventDisableTiming) != cudaSuccess) use_fork = 0;
        if (!use_fork) s2 = nullptr;
        cudaGetLastError();
    }
    cudaStream_t sp = use_fork ? s2 : (cudaStream_t)0;

    const int TB = 256;
    dim3 gg1((N_NODES + 127) / 128, 1);
    int agg_blocks = (N_NODES * 32 + TB - 1) / TB;

    // ---- fork: CSR/prep chain on sp (touches only edge_index + prep scratch)
    if (use_fork) {
        cudaEventRecord(ev_fork, 0);
        cudaStreamWaitEvent(sp, ev_fork, 0);
    }
    k_detect<<<1, 32, 0, sp>>>((const int*)ei);
    cudaMemsetAsync(p_deg, 0, (size_t)N_NODES * sizeof(float), sp);
    k_deg<<<(N_EDGES + TB - 1) / TB, TB, 0, sp>>>(ei);
    k_scan1<<<SCAN_NB, 1024, 0, sp>>>();   // also writes g_dinv
    k_scan2<<<1, 128, 0, sp>>>();
    k_scan3<<<SCAN_NB, 1024, 0, sp>>>();
    k_fill<<<(N_EDGES + TB - 1) / TB, TB, 0, sp>>>(ei);
    if (use_fork) cudaEventRecord(ev_join, sp);

    // ---- main stream meanwhile: layer-1 GEMM (fp16 out) + weight collapse
    k_gemm<<<gg1, TB>>>(x, W1, nullptr, nullptr, h16, N_NODES, IN_CH, HID1, 0);
    k_w34<<<64, 64>>>(W3, b3, W4, b4);

    // ---- join
    if (use_fork) cudaStreamWaitEvent((cudaStream_t)0, ev_join, 0);

    // layer 1 aggregate (fp16 gather -> fp32 h2)
    k_agg<<<agg_blocks, TB>>>(h16, b1, h2);

    // layer 2: GEMM (fp16 out) ; aggregate
    k_gemm<<<gg1, TB>>>(h2, W2, nullptr, nullptr, h16, N_NODES, HID1, HID2, 0);
    k_agg<<<agg_blocks, TB>>>(h16, b2, h2);

    // collapsed layers 3+4 + fused log_softmax (all fp32)
    k_gemm<<<gg1, TB>>>(h2, W34, b34, out, nullptr, N_NODES, HID2, OUT_CH, 1);
}

// round 13
// speedup vs baseline: 1.0657x; 1.0657x over previous
#include <cuda_runtime.h>
#include <cuda_fp16.h>

#define N_NODES 100000
#define N_EDGES 1600000
#define IN_CH 128
#define HID1 64
#define HID2 64
#define HID3 256
#define OUT_CH 64
#define SCAN_NB ((N_NODES + 1023) / 1024)   // 98

// ---------------- scratch (device globals; no allocation allowed) ----------------
__device__ float g_deg[N_NODES];
__device__ float g_dinv[N_NODES];
__device__ int   g_rs[N_NODES];                // CSR row start (exclusive scan)
__device__ int   g_cur[N_NODES];               // scatter cursors
__device__ int   g_bsum[128];                  // per-block scan sums
__device__ int   g_boff[128];                  // per-block offsets
__device__ int2  g_csr[N_EDGES];               // {src, norm-as-bits} grouped by dst
__device__ float g_h1[(size_t)N_NODES * 64];   // GEMM output (gather source)
__device__ float g_h2[(size_t)N_NODES * 64];   // agg output
__device__ float g_W34[64 * 64];               // W3 @ W4 collapsed weight
__device__ float g_b34[64];                    // b3 @ W4 + b4
__device__ int   g_is64;                       // edge_index dtype flag

// ---------------- index dtype detection ----------------
__global__ void k_detect(const int* ei) {
    if (threadIdx.x == 0 && blockIdx.x == 0) {
        int is64 = 1;
        #pragma unroll 1
        for (int i = 0; i < 64; i++) {
            if (ei[2 * i + 1] != 0) { is64 = 0; break; }
        }
        g_is64 = is64;
    }
}

__device__ __forceinline__ int load_idx(const void* ei, long long i, int is64) {
    if (is64) return (int)__ldg(((const long long*)ei) + i);
    return __ldg(((const int*)ei) + i);
}

// ---------------- degree ----------------
__global__ void k_deg(const void* __restrict__ ei) {
    int e = blockIdx.x * blockDim.x + threadIdx.x;
    if (e >= N_EDGES) return;
    int d = load_idx(ei, (long long)N_EDGES + e, g_is64);
    atomicAdd(&g_deg[d], 1.0f);
}

// ---------------- collapse layers 3+4: W34 = W3@W4, b34 = b3@W4 + b4 ----------------
__global__ __launch_bounds__(64) void k_w34(const float* __restrict__ W3,
                                            const float* __restrict__ b3,
                                            const float* __restrict__ W4,
                                            const float* __restrict__ b4) {
    int i = blockIdx.x;
    int j = threadIdx.x;
    const float* w3r = W3 + (size_t)i * HID3;
    float acc = 0.0f;
    #pragma unroll 8
    for (int k = 0; k < HID3; k++) acc += w3r[k] * W4[(size_t)k * OUT_CH + j];
    g_W34[i * 64 + j] = acc;
    if (i == 0) {
        float bb = 0.0f;
        #pragma unroll 8
        for (int k = 0; k < HID3; k++) bb += b3[k] * W4[(size_t)k * OUT_CH + j];
        g_b34[j] = bb + b4[j];
    }
}

// ---------------- scan phase 1 (+ fused dinv) ----------------
__global__ __launch_bounds__(1024) void k_scan1() {
    __shared__ int s[1024];
    int t = threadIdx.x;
    int i = blockIdx.x * 1024 + t;
    float dg = (i < N_NODES) ? g_deg[i] : 0.0f;
    int v = (int)dg;
    if (i < N_NODES) g_dinv[i] = rsqrtf(dg + 1.0f);
    s[t] = v;
    __syncthreads();
    #pragma unroll 1
    for (int off = 1; off < 1024; off <<= 1) {
        int x = (t >= off) ? s[t - off] : 0;
        __syncthreads();
        s[t] += x;
        __syncthreads();
    }
    if (i < N_NODES) g_rs[i] = s[t] - v;   // exclusive within block
    if (t == 1023) g_bsum[blockIdx.x] = s[1023];
}

__global__ __launch_bounds__(128) void k_scan2() {
    __shared__ int s[128];
    int t = threadIdx.x;
    int v = (t < SCAN_NB) ? g_bsum[t] : 0;
    s[t] = v;
    __syncthreads();
    #pragma unroll 1
    for (int off = 1; off < 128; off <<= 1) {
        int x = (t >= off) ? s[t - off] : 0;
        __syncthreads();
        s[t] += x;
        __syncthreads();
    }
    if (t < SCAN_NB) g_boff[t] = s[t] - v;
}

__global__ __launch_bounds__(1024) void k_scan3() {
    int i = blockIdx.x * 1024 + threadIdx.x;
    if (i >= N_NODES) return;
    int r = g_rs[i] + g_boff[blockIdx.x];
    g_rs[i] = r;
    g_cur[i] = r;
}

// ---------------- fill CSR ----------------
__global__ void k_fill(const void* __restrict__ ei) {
    int e = blockIdx.x * blockDim.x + threadIdx.x;
    if (e >= N_EDGES) return;
    int is64 = g_is64;
    int s = load_idx(ei, e, is64);
    int d = load_idx(ei, (long long)N_EDGES + e, is64);
    float norm = g_dinv[s] * g_dinv[d];
    int pos = atomicAdd(&g_cur[d], 1);
    g_csr[pos] = make_int2(s, __float_as_int(norm));
}

// ---------------- fused aggregate + self-loop + bias + relu ----------------
// 16 lanes per node, one LDG.128 per gathered row per edge (minimizes LSU
// instruction count — the binding resource per R11 post-mortem). fp32 all.
__global__ __launch_bounds__(256) void k_agg(const float* __restrict__ h,
                                             const float* __restrict__ bias,
                                             float* __restrict__ out) {
    int t = blockIdx.x * 256 + threadIdx.x;
    int node = t >> 4;         // 16 threads per node
    int sl = threadIdx.x & 15; // sub-lane: owns channels 4*sl..4*sl+3
    if (node >= N_NODES) return;
    int start = g_rs[node];
    int end = start + (int)g_deg[node];
    float di = g_dinv[node];
    float slw = di * di;
    const float4* hrow = (const float4*)(h + ((size_t)node << 6));
    float4 a = __ldg(&hrow[sl]);
    float4 acc = make_float4(a.x * slw, a.y * slw, a.z * slw, a.w * slw);
    int e = start;
    for (; e + 3 < end; e += 4) {
        int2 r0 = __ldg(&g_csr[e + 0]);
        int2 r1 = __ldg(&g_csr[e + 1]);
        int2 r2 = __ldg(&g_csr[e + 2]);
        int2 r3 = __ldg(&g_csr[e + 3]);
        float4 v0 = __ldg(&((const float4*)(h + ((size_t)r0.x << 6)))[sl]);
        float4 v1 = __ldg(&((const float4*)(h + ((size_t)r1.x << 6)))[sl]);
        float4 v2 = __ldg(&((const float4*)(h + ((size_t)r2.x << 6)))[sl]);
        float4 v3 = __ldg(&((const float4*)(h + ((size_t)r3.x << 6)))[sl]);
        float n0 = __int_as_float(r0.y), n1 = __int_as_float(r1.y);
        float n2 = __int_as_float(r2.y), n3 = __int_as_float(r3.y);
        acc.x += v0.x * n0; acc.y += v0.y * n0; acc.z += v0.z * n0; acc.w += v0.w * n0;
        acc.x += v1.x * n1; acc.y += v1.y * n1; acc.z += v1.z * n1; acc.w += v1.w * n1;
        acc.x += v2.x * n2; acc.y += v2.y * n2; acc.z += v2.z * n2; acc.w += v2.w * n2;
        acc.x += v3.x * n3; acc.y += v3.y * n3; acc.z += v3.z * n3; acc.w += v3.w * n3;
    }
    for (; e < end; e++) {
        int2 r = __ldg(&g_csr[e]);
        float n = __int_as_float(r.y);
        float4 v = __ldg(&((const float4*)(h + ((size_t)r.x << 6)))[sl]);
        acc.x += v.x * n; acc.y += v.y * n; acc.z += v.z * n; acc.w += v.w * n;
    }
    float4 bv = __ldg(&((const float4*)bias)[sl]);
    float4 o;
    o.x = fmaxf(acc.x + bv.x, 0.0f);
    o.y = fmaxf(acc.y + bv.y, 0.0f);
    o.z = fmaxf(acc.z + bv.z, 0.0f);
    o.w = fmaxf(acc.w + bv.w, 0.0f);
    ((float4*)(out + ((size_t)node << 6)))[sl] = o;
}

// ---------------- SGEMM: C[N,NOUT] = A[N,K] @ W[K,NOUT] (+bias) (+lsm) ----------------
// BM=128, BN=64, BK=16, 256 threads, 8x4 microtile, double-buffered smem.
// lsm=1 requires NOUT==64 and gridDim.y==1 (full row in one block).
__global__ __launch_bounds__(256) void k_gemm(const float* __restrict__ A,
                                              const float* __restrict__ W,
                                              const float* __restrict__ bias,
                                              float* __restrict__ C,
                                              int N, int K, int NOUT, int lsm) {
    __shared__ float As[2][16][128];
    __shared__ float Bs[2][16][64];

    int r0 = blockIdx.x * 128;
    int c0 = blockIdx.y * 64;
    int tid = threadIdx.x;
    int tx = tid & 15;
    int ty = tid >> 4;

    int arow = tid >> 1;
    int ak8  = (tid & 1) << 3;
    int wrow = tid >> 4;
    int wc4  = (tid & 15) << 2;

    float acc[8][4];
    #pragma unroll
    for (int i = 0; i < 8; i++)
        #pragma unroll
        for (int j = 0; j < 4; j++) acc[i][j] = 0.0f;

    int nsteps = K >> 4;
    int gr_a = r0 + arow;

    // preload tile 0
    {
        float4 a0 = make_float4(0.f, 0.f, 0.f, 0.f);
        float4 a1 = make_float4(0.f, 0.f, 0.f, 0.f);
        if (gr_a < N) {
            const float* ap = A + (size_t)gr_a * K + ak8;
            a0 = *(const float4*)ap;
            a1 = *(const float4*)(ap + 4);
        }
        As[0][ak8 + 0][arow] = a0.x; As[0][ak8 + 1][arow] = a0.y;
        As[0][ak8 + 2][arow] = a0.z; As[0][ak8 + 3][arow] = a0.w;
        As[0][ak8 + 4][arow] = a1.x; As[0][ak8 + 5][arow] = a1.y;
        As[0][ak8 + 6][arow] = a1.z; As[0][ak8 + 7][arow] = a1.w;
        *(float4*)&Bs[0][wrow][wc4] = *(const float4*)&W[(size_t)wrow * NOUT + c0 + wc4];
    }
    __syncthreads();

    for (int t = 0; t < nsteps; t++) {
        int cur = t & 1;
        float4 a0, a1, wv;
        bool have_next = (t + 1 < nsteps);
        if (have_next) {
            int kk = (t + 1) << 4;
            a0 = make_float4(0.f, 0.f, 0.f, 0.f);
            a1 = make_float4(0.f, 0.f, 0.f, 0.f);
            if (gr_a < N) {
                const float* ap = A + (size_t)gr_a * K + kk + ak8;
                a0 = *(const float4*)ap;
                a1 = *(const float4*)(ap + 4);
            }
            wv = *(const float4*)&W[(size_t)(kk + wrow) * NOUT + c0 + wc4];
        }

        #pragma unroll
        for (int k = 0; k < 16; k++) {
            float4 b = *(const float4*)&Bs[cur][k][tx * 4];
            float ar[8];
            #pragma unroll
            for (int i = 0; i < 8; i++) ar[i] = As[cur][k][ty * 8 + i];
            #pragma unroll
            for (int i = 0; i < 8; i++) {
                acc[i][0] += ar[i] * b.x;
                acc[i][1] += ar[i] * b.y;
                acc[i][2] += ar[i] * b.z;
                acc[i][3] += ar[i] * b.w;
            }
        }

        if (have_next) {
            int nxt = cur ^ 1;
            As[nxt][ak8 + 0][arow] = a0.x; As[nxt][ak8 + 1][arow] = a0.y;
            As[nxt][ak8 + 2][arow] = a0.z; As[nxt][ak8 + 3][arow] = a0.w;
            As[nxt][ak8 + 4][arow] = a1.x; As[nxt][ak8 + 5][arow] = a1.y;
            As[nxt][ak8 + 6][arow] = a1.z; As[nxt][ak8 + 7][arow] = a1.w;
            *(float4*)&Bs[nxt][wrow][wc4] = wv;
            __syncthreads();
        }
    }

    float4 bv = make_float4(0.f, 0.f, 0.f, 0.f);
    if (bias) bv = *(const float4*)&bias[c0 + tx * 4];

    if (!lsm) {
        #pragma unroll
        for (int i = 0; i < 8; i++) {
            int gr = r0 + ty * 8 + i;
            if (gr < N) {
                *(float4*)&C[(size_t)gr * NOUT + c0 + tx * 4] =
                    make_float4(acc[i][0] + bv.x, acc[i][1] + bv.y,
                                acc[i][2] + bv.z, acc[i][3] + bv.w);
            }
        }
    } else {
        // fused log_softmax over the 64 cols of each row (16 tx lanes x 4 cols,
        // within one half-warp; xor offsets 8/4/2/1 stay inside the row).
        #pragma unroll
        for (int i = 0; i < 8; i++) {
            float v0 = acc[i][0] + bv.x;
            float v1 = acc[i][1] + bv.y;
            float v2 = acc[i][2] + bv.z;
            float v3 = acc[i][3] + bv.w;
            float m = fmaxf(fmaxf(v0, v1), fmaxf(v2, v3));
            #pragma unroll
            for (int o = 8; o; o >>= 1) m = fmaxf(m, __shfl_xor_sync(0xffffffffu, m, o));
            float s = expf(v0 - m) + expf(v1 - m) + expf(v2 - m) + expf(v3 - m);
            #pragma unroll
            for (int o = 8; o; o >>= 1) s += __shfl_xor_sync(0xffffffffu, s, o);
            float lse = m + logf(s);
            int gr = r0 + ty * 8 + i;
            if (gr < N) {
                *(float4*)&C[(size_t)gr * 64 + tx * 4] =
                    make_float4(v0 - lse, v1 - lse, v2 - lse, v3 - lse);
            }
        }
    }
}

// ---------------- launch ----------------
extern "C" void kernel_launch(void* const* d_in, const int* in_sizes, int n_in,
                              void* d_out, int out_size) {
    const float* x  = (const float*)d_in[0];
    const void*  ei = d_in[1];
    const float* W1 = (const float*)d_in[2];
    const float* b1 = (const float*)d_in[3];
    const float* W2 = (const float*)d_in[4];
    const float* b2 = (const float*)d_in[5];
    const float* W3 = (const float*)d_in[6];
    const float* b3 = (const float*)d_in[7];
    const float* W4 = (const float*)d_in[8];
    const float* b4 = (const float*)d_in[9];
    float* out = (float*)d_out;

    void *p_deg, *p_h1, *p_h2, *p_w34, *p_b34;
    cudaGetSymbolAddress(&p_deg, g_deg);
    cudaGetSymbolAddress(&p_h1, g_h1);
    cudaGetSymbolAddress(&p_h2, g_h2);
    cudaGetSymbolAddress(&p_w34, g_W34);
    cudaGetSymbolAddress(&p_b34, g_b34);
    float* h1  = (float*)p_h1;
    float* h2  = (float*)p_h2;
    float* W34 = (float*)p_w34;
    float* b34 = (float*)p_b34;

    // Side stream + events for fork-join (created once, pre-capture). Fallback
    // to serial single-stream ordering if creation fails.
    static cudaStream_t s2 = nullptr;
    static cudaEvent_t ev_fork = nullptr, ev_join = nullptr;
    static int use_fork = -1;
    if (use_fork < 0) {
        use_fork = 1;
        if (cudaStreamCreateWithFlags(&s2, cudaStreamNonBlocking) != cudaSuccess) use_fork = 0;
        if (use_fork && cudaEventCreateWithFlags(&ev_fork, cudaEventDisableTiming) != cudaSuccess) use_fork = 0;
        if (use_fork && cudaEventCreateWithFlags(&ev_join, cudaEventDisableTiming) != cudaSuccess) use_fork = 0;
        if (!use_fork) s2 = nullptr;
        cudaGetLastError();
    }
    cudaStream_t sp = use_fork ? s2 : (cudaStream_t)0;

    const int TB = 256;
    dim3 gg1((N_NODES + 127) / 128, 1);
    int agg_blocks = (N_NODES * 16 + TB - 1) / TB;   // 16 threads per node

    // ---- fork: CSR/prep chain on sp (touches only edge_index + prep scratch)
    if (use_fork) {
        cudaEventRecord(ev_fork, 0);
        cudaStreamWaitEvent(sp, ev_fork, 0);
    }
    k_detect<<<1, 32, 0, sp>>>((const int*)ei);
    cudaMemsetAsync(p_deg, 0, (size_t)N_NODES * sizeof(float), sp);
    k_deg<<<(N_EDGES + TB - 1) / TB, TB, 0, sp>>>(ei);
    k_scan1<<<SCAN_NB, 1024, 0, sp>>>();   // also writes g_dinv
    k_scan2<<<1, 128, 0, sp>>>();
    k_scan3<<<SCAN_NB, 1024, 0, sp>>>();
    k_fill<<<(N_EDGES + TB - 1) / TB, TB, 0, sp>>>(ei);
    if (use_fork) cudaEventRecord(ev_join, sp);

    // ---- main stream meanwhile: layer-1 GEMM + weight collapse (disjoint data)
    k_gemm<<<gg1, TB>>>(x, W1, nullptr, h1, N_NODES, IN_CH, HID1, 0);
    k_w34<<<64, 64>>>(W3, b3, W4, b4);

    // ---- join
    if (use_fork) cudaStreamWaitEvent((cudaStream_t)0, ev_join, 0);

    // layer 1 aggregate
    k_agg<<<agg_blocks, TB>>>(h1, b1, h2);

    // layer 2
    k_gemm<<<gg1, TB>>>(h2, W2, nullptr, h1, N_NODES, HID1, HID2, 0);
    k_agg<<<agg_blocks, TB>>>(h1, b2, h2);

    // collapsed layers 3+4 + fused log_softmax
    k_gemm<<<gg1, TB>>>(h2, W34, b34, out, N_NODES, HID2, OUT_CH, 1);
}

// round 14
// speedup vs baseline: 1.0741x; 1.0079x over previous
#include <cuda_runtime.h>
#include <cuda_fp16.h>

#define N_NODES 100000
#define N_EDGES 1600000
#define IN_CH 128
#define HID1 64
#define HID2 64
#define HID3 256
#define OUT_CH 64
#define SCAN_NB ((N_NODES + 1023) / 1024)   // 98

// ---------------- scratch (device globals; no allocation allowed) ----------------
__device__ float g_deg[N_NODES];
__device__ float g_dinv[N_NODES];
__device__ int   g_rs[N_NODES];                // CSR row start (exclusive scan)
__device__ int   g_cur[N_NODES];               // scatter cursors
__device__ int   g_bsum[128];                  // per-block scan sums
__device__ int   g_boff[128];                  // per-block offsets
__device__ int2  g_csr[N_EDGES];               // {src, norm-as-bits} grouped by dst
__device__ float g_h1[(size_t)N_NODES * 64];   // GEMM output (gather source)
__device__ float g_h2[(size_t)N_NODES * 64];   // agg output
__device__ float g_W34[64 * 64];               // W3 @ W4 collapsed weight
__device__ float g_b34[64];                    // b3 @ W4 + b4
__device__ int   g_is64;                       // edge_index dtype flag

// ---------------- packed f32x2 helpers (B300 FFMA2 path, PTX-only) ----------------
__device__ __forceinline__ void fma_f32x2(unsigned long long& d,
                                          unsigned long long a,
                                          unsigned long long b) {
    asm("fma.rn.f32x2 %0, %1, %2, %0;" : "+l"(d) : "l"(a), "l"(b));
}
__device__ __forceinline__ unsigned long long dup_f32(float f) {
    unsigned long long r;
    asm("mov.b64 %0, {%1, %1};" : "=l"(r) : "f"(f));
    return r;
}
__device__ __forceinline__ float2 unpack_f32x2(unsigned long long v) {
    float2 r;
    asm("mov.b64 {%0, %1}, %2;" : "=f"(r.x), "=f"(r.y) : "l"(v));
    return r;
}

// ---------------- index dtype detection ----------------
__global__ void k_detect(const int* ei) {
    if (threadIdx.x == 0 && blockIdx.x == 0) {
        int is64 = 1;
        #pragma unroll 1
        for (int i = 0; i < 64; i++) {
            if (ei[2 * i + 1] != 0) { is64 = 0; break; }
        }
        g_is64 = is64;
    }
}

__device__ __forceinline__ int load_idx(const void* ei, long long i, int is64) {
    if (is64) return (int)__ldg(((const long long*)ei) + i);
    return __ldg(((const int*)ei) + i);
}

// ---------------- degree ----------------
__global__ void k_deg(const void* __restrict__ ei) {
    int e = blockIdx.x * blockDim.x + threadIdx.x;
    if (e >= N_EDGES) return;
    int d = load_idx(ei, (long long)N_EDGES + e, g_is64);
    atomicAdd(&g_deg[d], 1.0f);
}

// ---------------- collapse layers 3+4: W34 = W3@W4, b34 = b3@W4 + b4 ----------------
__global__ __launch_bounds__(64) void k_w34(const float* __restrict__ W3,
                                            const float* __restrict__ b3,
                                            const float* __restrict__ W4,
                                            const float* __restrict__ b4) {
    int i = blockIdx.x;
    int j = threadIdx.x;
    const float* w3r = W3 + (size_t)i * HID3;
    float acc = 0.0f;
    #pragma unroll 8
    for (int k = 0; k < HID3; k++) acc += w3r[k] * W4[(size_t)k * OUT_CH + j];
    g_W34[i * 64 + j] = acc;
    if (i == 0) {
        float bb = 0.0f;
        #pragma unroll 8
        for (int k = 0; k < HID3; k++) bb += b3[k] * W4[(size_t)k * OUT_CH + j];
        g_b34[j] = bb + b4[j];
    }
}

// ---------------- scan phase 1 (+ fused dinv) ----------------
__global__ __launch_bounds__(1024) void k_scan1() {
    __shared__ int s[1024];
    int t = threadIdx.x;
    int i = blockIdx.x * 1024 + t;
    float dg = (i < N_NODES) ? g_deg[i] : 0.0f;
    int v = (int)dg;
    if (i < N_NODES) g_dinv[i] = rsqrtf(dg + 1.0f);
    s[t] = v;
    __syncthreads();
    #pragma unroll 1
    for (int off = 1; off < 1024; off <<= 1) {
        int x = (t >= off) ? s[t - off] : 0;
        __syncthreads();
        s[t] += x;
        __syncthreads();
    }
    if (i < N_NODES) g_rs[i] = s[t] - v;   // exclusive within block
    if (t == 1023) g_bsum[blockIdx.x] = s[1023];
}

__global__ __launch_bounds__(128) void k_scan2() {
    __shared__ int s[128];
    int t = threadIdx.x;
    int v = (t < SCAN_NB) ? g_bsum[t] : 0;
    s[t] = v;
    __syncthreads();
    #pragma unroll 1
    for (int off = 1; off < 128; off <<= 1) {
        int x = (t >= off) ? s[t - off] : 0;
        __syncthreads();
        s[t] += x;
        __syncthreads();
    }
    if (t < SCAN_NB) g_boff[t] = s[t] - v;
}

__global__ __launch_bounds__(1024) void k_scan3() {
    int i = blockIdx.x * 1024 + threadIdx.x;
    if (i >= N_NODES) return;
    int r = g_rs[i] + g_boff[blockIdx.x];
    g_rs[i] = r;
    g_cur[i] = r;
}

// ---------------- fill CSR ----------------
__global__ void k_fill(const void* __restrict__ ei) {
    int e = blockIdx.x * blockDim.x + threadIdx.x;
    if (e >= N_EDGES) return;
    int is64 = g_is64;
    int s = load_idx(ei, e, is64);
    int d = load_idx(ei, (long long)N_EDGES + e, is64);
    float norm = g_dinv[s] * g_dinv[d];
    int pos = atomicAdd(&g_cur[d], 1);
    g_csr[pos] = make_int2(s, __float_as_int(norm));
}

// ---------------- fused aggregate + self-loop + bias + relu ----------------
// 16 lanes per node, one LDG.128 per gathered row per edge. fp32 all.
__global__ __launch_bounds__(256) void k_agg(const float* __restrict__ h,
                                             const float* __restrict__ bias,
                                             float* __restrict__ out) {
    int t = blockIdx.x * 256 + threadIdx.x;
    int node = t >> 4;         // 16 threads per node
    int sl = threadIdx.x & 15; // sub-lane: owns channels 4*sl..4*sl+3
    if (node >= N_NODES) return;
    int start = g_rs[node];
    int end = start + (int)g_deg[node];
    float di = g_dinv[node];
    float slw = di * di;
    const float4* hrow = (const float4*)(h + ((size_t)node << 6));
    float4 a = __ldg(&hrow[sl]);
    float4 acc = make_float4(a.x * slw, a.y * slw, a.z * slw, a.w * slw);
    int e = start;
    for (; e + 3 < end; e += 4) {
        int2 r0 = __ldg(&g_csr[e + 0]);
        int2 r1 = __ldg(&g_csr[e + 1]);
        int2 r2 = __ldg(&g_csr[e + 2]);
        int2 r3 = __ldg(&g_csr[e + 3]);
        float4 v0 = __ldg(&((const float4*)(h + ((size_t)r0.x << 6)))[sl]);
        float4 v1 = __ldg(&((const float4*)(h + ((size_t)r1.x << 6)))[sl]);
        float4 v2 = __ldg(&((const float4*)(h + ((size_t)r2.x << 6)))[sl]);
        float4 v3 = __ldg(&((const float4*)(h + ((size_t)r3.x << 6)))[sl]);
        float n0 = __int_as_float(r0.y), n1 = __int_as_float(r1.y);
        float n2 = __int_as_float(r2.y), n3 = __int_as_float(r3.y);
        acc.x += v0.x * n0; acc.y += v0.y * n0; acc.z += v0.z * n0; acc.w += v0.w * n0;
        acc.x += v1.x * n1; acc.y += v1.y * n1; acc.z += v1.z * n1; acc.w += v1.w * n1;
        acc.x += v2.x * n2; acc.y += v2.y * n2; acc.z += v2.z * n2; acc.w += v2.w * n2;
        acc.x += v3.x * n3; acc.y += v3.y * n3; acc.z += v3.z * n3; acc.w += v3.w * n3;
    }
    for (; e < end; e++) {
        int2 r = __ldg(&g_csr[e]);
        float n = __int_as_float(r.y);
        float4 v = __ldg(&((const float4*)(h + ((size_t)r.x << 6)))[sl]);
        acc.x += v.x * n; acc.y += v.y * n; acc.z += v.z * n; acc.w += v.w * n;
    }
    float4 bv = __ldg(&((const float4*)bias)[sl]);
    float4 o;
    o.x = fmaxf(acc.x + bv.x, 0.0f);
    o.y = fmaxf(acc.y + bv.y, 0.0f);
    o.z = fmaxf(acc.z + bv.z, 0.0f);
    o.w = fmaxf(acc.w + bv.w, 0.0f);
    ((float4*)(out + ((size_t)node << 6)))[sl] = o;
}

// ---------------- SGEMM: C[N,NOUT] = A[N,K] @ W[K,NOUT] (+bias) (+lsm) ----------------
// BM=128, BN=64, BK=16, 256 threads, 8x4 microtile, double-buffered smem.
// Inner loop uses packed fma.rn.f32x2 (FFMA2): accumulators hold row-pairs.
// lsm=1 requires NOUT==64 and gridDim.y==1 (full row in one block).
__global__ __launch_bounds__(256) void k_gemm(const float* __restrict__ A,
                                              const float* __restrict__ W,
                                              const float* __restrict__ bias,
                                              float* __restrict__ C,
                                              int N, int K, int NOUT, int lsm) {
    __shared__ __align__(16) float As[2][16][128];
    __shared__ __align__(16) float Bs[2][16][64];

    int r0 = blockIdx.x * 128;
    int c0 = blockIdx.y * 64;
    int tid = threadIdx.x;
    int tx = tid & 15;
    int ty = tid >> 4;

    int arow = tid >> 1;
    int ak8  = (tid & 1) << 3;
    int wrow = tid >> 4;
    int wc4  = (tid & 15) << 2;

    // accp[p][j]: packed fp32x2 accumulator for rows (ty*8+2p, ty*8+2p+1), col j
    unsigned long long accp[4][4];
    #pragma unroll
    for (int p = 0; p < 4; p++)
        #pragma unroll
        for (int j = 0; j < 4; j++) accp[p][j] = 0ULL;

    int nsteps = K >> 4;
    int gr_a = r0 + arow;

    // preload tile 0
    {
        float4 a0 = make_float4(0.f, 0.f, 0.f, 0.f);
        float4 a1 = make_float4(0.f, 0.f, 0.f, 0.f);
        if (gr_a < N) {
            const float* ap = A + (size_t)gr_a * K + ak8;
            a0 = *(const float4*)ap;
            a1 = *(const float4*)(ap + 4);
        }
        As[0][ak8 + 0][arow] = a0.x; As[0][ak8 + 1][arow] = a0.y;
        As[0][ak8 + 2][arow] = a0.z; As[0][ak8 + 3][arow] = a0.w;
        As[0][ak8 + 4][arow] = a1.x; As[0][ak8 + 5][arow] = a1.y;
        As[0][ak8 + 6][arow] = a1.z; As[0][ak8 + 7][arow] = a1.w;
        *(float4*)&Bs[0][wrow][wc4] = *(const float4*)&W[(size_t)wrow * NOUT + c0 + wc4];
    }
    __syncthreads();

    for (int t = 0; t < nsteps; t++) {
        int cur = t & 1;
        float4 a0, a1, wv;
        bool have_next = (t + 1 < nsteps);
        if (have_next) {
            int kk = (t + 1) << 4;
            a0 = make_float4(0.f, 0.f, 0.f, 0.f);
            a1 = make_float4(0.f, 0.f, 0.f, 0.f);
            if (gr_a < N) {
                const float* ap = A + (size_t)gr_a * K + kk + ak8;
                a0 = *(const float4*)ap;
                a1 = *(const float4*)(ap + 4);
            }
            wv = *(const float4*)&W[(size_t)(kk + wrow) * NOUT + c0 + wc4];
        }

        #pragma unroll
        for (int k = 0; k < 16; k++) {
            float4 b = *(const float4*)&Bs[cur][k][tx * 4];
            // A row-pairs for this thread: rows ty*8 .. ty*8+7, packed 2 at a time
            ulonglong2 av0 = *(const ulonglong2*)&As[cur][k][ty * 8];      // (r0,r1),(r2,r3)
            ulonglong2 av1 = *(const ulonglong2*)&As[cur][k][ty * 8 + 4];  // (r4,r5),(r6,r7)
            unsigned long long bd0 = dup_f32(b.x);
            unsigned long long bd1 = dup_f32(b.y);
            unsigned long long bd2 = dup_f32(b.z);
            unsigned long long bd3 = dup_f32(b.w);
            fma_f32x2(accp[0][0], av0.x, bd0);
            fma_f32x2(accp[0][1], av0.x, bd1);
            fma_f32x2(accp[0][2], av0.x, bd2);
            fma_f32x2(accp[0][3], av0.x, bd3);
            fma_f32x2(accp[1][0], av0.y, bd0);
            fma_f32x2(accp[1][1], av0.y, bd1);
            fma_f32x2(accp[1][2], av0.y, bd2);
            fma_f32x2(accp[1][3], av0.y, bd3);
            fma_f32x2(accp[2][0], av1.x, bd0);
            fma_f32x2(accp[2][1], av1.x, bd1);
            fma_f32x2(accp[2][2], av1.x, bd2);
            fma_f32x2(accp[2][3], av1.x, bd3);
            fma_f32x2(accp[3][0], av1.y, bd0);
            fma_f32x2(accp[3][1], av1.y, bd1);
            fma_f32x2(accp[3][2], av1.y, bd2);
            fma_f32x2(accp[3][3], av1.y, bd3);
        }

        if (have_next) {
            int nxt = cur ^ 1;
            As[nxt][ak8 + 0][arow] = a0.x; As[nxt][ak8 + 1][arow] = a0.y;
            As[nxt][ak8 + 2][arow] = a0.z; As[nxt][ak8 + 3][arow] = a0.w;
            As[nxt][ak8 + 4][arow] = a1.x; As[nxt][ak8 + 5][arow] = a1.y;
            As[nxt][ak8 + 6][arow] = a1.z; As[nxt][ak8 + 7][arow] = a1.w;
            *(float4*)&Bs[nxt][wrow][wc4] = wv;
            __syncthreads();
        }
    }

    // unpack accumulators to acc[8][4]
    float acc[8][4];
    #pragma unroll
    for (int p = 0; p < 4; p++)
        #pragma unroll
        for (int j = 0; j < 4; j++) {
            float2 v = unpack_f32x2(accp[p][j]);
            acc[2 * p + 0][j] = v.x;
            acc[2 * p + 1][j] = v.y;
        }

    float4 bv = make_float4(0.f, 0.f, 0.f, 0.f);
    if (bias) bv = *(const float4*)&bias[c0 + tx * 4];

    if (!lsm) {
        #pragma unroll
        for (int i = 0; i < 8; i++) {
            int gr = r0 + ty * 8 + i;
            if (gr < N) {
                *(float4*)&C[(size_t)gr * NOUT + c0 + tx * 4] =
                    make_float4(acc[i][0] + bv.x, acc[i][1] + bv.y,
                                acc[i][2] + bv.z, acc[i][3] + bv.w);
            }
        }
    } else {
        // fused log_softmax over the 64 cols of each row (16 tx lanes x 4 cols,
        // within one half-warp; xor offsets 8/4/2/1 stay inside the row).
        #pragma unroll
        for (int i = 0; i < 8; i++) {
            float v0 = acc[i][0] + bv.x;
            float v1 = acc[i][1] + bv.y;
            float v2 = acc[i][2] + bv.z;
            float v3 = acc[i][3] + bv.w;
            float m = fmaxf(fmaxf(v0, v1), fmaxf(v2, v3));
            #pragma unroll
            for (int o = 8; o; o >>= 1) m = fmaxf(m, __shfl_xor_sync(0xffffffffu, m, o));
            float s = expf(v0 - m) + expf(v1 - m) + expf(v2 - m) + expf(v3 - m);
            #pragma unroll
            for (int o = 8; o; o >>= 1) s += __shfl_xor_sync(0xffffffffu, s, o);
            float lse = m + logf(s);
            int gr = r0 + ty * 8 + i;
            if (gr < N) {
                *(float4*)&C[(size_t)gr * 64 + tx * 4] =
                    make_float4(v0 - lse, v1 - lse, v2 - lse, v3 - lse);
            }
        }
    }
}

// ---------------- launch ----------------
extern "C" void kernel_launch(void* const* d_in, const int* in_sizes, int n_in,
                              void* d_out, int out_size) {
    const float* x  = (const float*)d_in[0];
    const void*  ei = d_in[1];
    const float* W1 = (const float*)d_in[2];
    const float* b1 = (const float*)d_in[3];
    const float* W2 = (const float*)d_in[4];
    const float* b2 = (const float*)d_in[5];
    const float* W3 = (const float*)d_in[6];
    const float* b3 = (const float*)d_in[7];
    const float* W4 = (const float*)d_in[8];
    const float* b4 = (const float*)d_in[9];
    float* out = (float*)d_out;

    void *p_deg, *p_h1, *p_h2, *p_w34, *p_b34;
    cudaGetSymbolAddress(&p_deg, g_deg);
    cudaGetSymbolAddress(&p_h1, g_h1);
    cudaGetSymbolAddress(&p_h2, g_h2);
    cudaGetSymbolAddress(&p_w34, g_W34);
    cudaGetSymbolAddress(&p_b34, g_b34);
    float* h1  = (float*)p_h1;
    float* h2  = (float*)p_h2;
    float* W34 = (float*)p_w34;
    float* b34 = (float*)p_b34;

    // Side stream + events for fork-join (created once, pre-capture). Fallback
    // to serial single-stream ordering if creation fails.
    static cudaStream_t s2 = nullptr;
    static cudaEvent_t ev_fork = nullptr, ev_join = nullptr;
    static int use_fork = -1;
    if (use_fork < 0) {
        use_fork = 1;
        if (cudaStreamCreateWithFlags(&s2, cudaStreamNonBlocking) != cudaSuccess) use_fork = 0;
        if (use_fork && cudaEventCreateWithFlags(&ev_fork, cudaEventDisableTiming) != cudaSuccess) use_fork = 0;
        if (use_fork && cudaEventCreateWithFlags(&ev_join, cudaEventDisableTiming) != cudaSuccess) use_fork = 0;
        if (!use_fork) s2 = nullptr;
        cudaGetLastError();
    }
    cudaStream_t sp = use_fork ? s2 : (cudaStream_t)0;

    const int TB = 256;
    dim3 gg1((N_NODES + 127) / 128, 1);
    int agg_blocks = (N_NODES * 16 + TB - 1) / TB;   // 16 threads per node

    // ---- fork: CSR/prep chain on sp (touches only edge_index + prep scratch)
    if (use_fork) {
        cudaEventRecord(ev_fork, 0);
        cudaStreamWaitEvent(sp, ev_fork, 0);
    }
    k_detect<<<1, 32, 0, sp>>>((const int*)ei);
    cudaMemsetAsync(p_deg, 0, (size_t)N_NODES * sizeof(float), sp);
    k_deg<<<(N_EDGES + TB - 1) / TB, TB, 0, sp>>>(ei);
    k_scan1<<<SCAN_NB, 1024, 0, sp>>>();   // also writes g_dinv
    k_scan2<<<1, 128, 0, sp>>>();
    k_scan3<<<SCAN_NB, 1024, 0, sp>>>();
    k_fill<<<(N_EDGES + TB - 1) / TB, TB, 0, sp>>>(ei);
    if (use_fork) cudaEventRecord(ev_join, sp);

    // ---- main stream meanwhile: layer-1 GEMM + weight collapse (disjoint data)
    k_gemm<<<gg1, TB>>>(x, W1, nullptr, h1, N_NODES, IN_CH, HID1, 0);
    k_w34<<<64, 64>>>(W3, b3, W4, b4);

    // ---- join
    if (use_fork) cudaStreamWaitEvent((cudaStream_t)0, ev_join, 0);

    // layer 1 aggregate
    k_agg<<<agg_blocks, TB>>>(h1, b1, h2);

    // layer 2
    k_gemm<<<gg1, TB>>>(h2, W2, nullptr, h1, N_NODES, HID1, HID2, 0);
    k_agg<<<agg_blocks, TB>>>(h1, b2, h2);

    // collapsed layers 3+4 + fused log_softmax
    k_gemm<<<gg1, TB>>>(h2, W34, b34, out, N_NODES, HID2, OUT_CH, 1);
}